// round 1
// baseline (speedup 1.0000x reference)
#include <cuda_runtime.h>
#include <cstddef>

#define TT 64
#define LL 512
#define BB 512
#define START_TAG 62
#define STOP_TAG  63

// Scratch for per-batch partial results (allocation-free requirement).
__device__ float g_partials[BB];

__global__ void __launch_bounds__(TT, 8) crf_forward_kernel(
    const float* __restrict__ inputs,   // (B, L, T)
    const int*   __restrict__ tags,     // (B, L)
    const int*   __restrict__ mask,     // (B, L)
    const float* __restrict__ trans)    // (T, T)
{
    const int b   = blockIdx.x;
    const int tid = threadIdx.x;

    __shared__ __align__(16) float q_sh[TT];
    __shared__ float mf_sh[LL];
    __shared__ int   tags_sh[LL];
    __shared__ float red[TT];
    __shared__ float d0_sh;

    // Precompute exp of the transition row for destination tag = tid.
    // trans[i, j]: transition from j to i. Row START is -10000 -> expT = 0.
    float P[TT];
#pragma unroll
    for (int j = 0; j < TT; ++j)
        P[j] = __expf(trans[tid * TT + j]);

    // Stage mask (as float) and tags for this batch into shared.
    for (int t = tid; t < LL; t += TT) {
        mf_sh[t]   = (float)mask[b * LL + t];
        tags_sh[t] = tags[b * LL + t];
    }
    __syncthreads();

    const float* emit_ptr = inputs + (size_t)b * LL * TT + tid;

    // alpha_hat: normalized log-alpha for own tag; C: accumulated common offset.
    float a_hat = (tid == START_TAG) ? 0.0f : -10000.0f;
    float C = 0.0f;

    // Software prefetch of emissions, 2 steps ahead.
    float e_cur = emit_ptr[0];
    float e_nxt = emit_ptr[TT];

    for (int t = 0; t < LL; ++t) {
        float e_pf = (t + 2 < LL) ? emit_ptr[(t + 2) * TT] : 0.0f;

        q_sh[tid] = __expf(a_hat);
        __syncthreads();

        const float mf = mf_sh[t];
        float s;
        if (mf != 0.0f) {
            // s_i = sum_j expT[i,j] * q[j]   (pure FFMA, broadcast LDS.128)
            const float4* q4 = (const float4*)q_sh;
            float s0 = 0.f, s1 = 0.f, s2 = 0.f, s3 = 0.f;
#pragma unroll
            for (int j = 0; j < TT / 4; ++j) {
                float4 qv = q4[j];
                s0 = fmaf(P[4 * j + 0], qv.x, s0);
                s1 = fmaf(P[4 * j + 1], qv.y, s1);
                s2 = fmaf(P[4 * j + 2], qv.z, s2);
                s3 = fmaf(P[4 * j + 3], qv.w, s3);
            }
            s = (s0 + s1) + (s2 + s3);
        } else {
            // masked step: new alpha = logsumexp_j(alpha[j]) for every i
            float acc = 0.f;
#pragma unroll
            for (int j = 0; j < TT; ++j) acc += q_sh[j];
            s = acc;
        }

        // delta (relative to old offset C): d_i = m*emit_i + log(s_i)
        float d = fmaf(mf, e_cur, __logf(s));
        d = fmaxf(d, -1.0e30f);          // kill -inf from dead START row
        if (tid == 0) d0_sh = d;
        __syncthreads();
        const float d0 = d0_sh;          // anchor broadcast
        a_hat = d - d0;
        C += d0;

        e_cur = e_nxt;
        e_nxt = e_pf;
    }

    // ---- log denominator: logsumexp(alpha + trans[STOP, :]) ----
    float term = a_hat + trans[STOP_TAG * TT + tid];
    red[tid] = term;
    __syncthreads();
#pragma unroll
    for (int off = TT / 2; off > 0; off >>= 1) {
        if (tid < off) red[tid] = fmaxf(red[tid], red[tid + off]);
        __syncthreads();
    }
    const float mx = red[0];
    __syncthreads();
    red[tid] = __expf(term - mx);
    __syncthreads();
#pragma unroll
    for (int off = TT / 2; off > 0; off >>= 1) {
        if (tid < off) red[tid] += red[tid + off];
        __syncthreads();
    }
    const float logden = C + mx + __logf(red[0]);
    __syncthreads();

    // ---- numerator path score (gold tags) ----
    float sc = 0.f;
    const float* in_b = inputs + (size_t)b * LL * TT;
    for (int t = tid; t < LL - 1; t += TT) {
        const int pt = tags_sh[t];
        const int nt = tags_sh[t + 1];
        sc += trans[nt * TT + pt] * mf_sh[t + 1] + in_b[t * TT + pt] * mf_sh[t];
    }
    red[tid] = sc;
    __syncthreads();
#pragma unroll
    for (int off = TT / 2; off > 0; off >>= 1) {
        if (tid < off) red[tid] += red[tid + off];
        __syncthreads();
    }
    if (tid == 0) {
        const int t0 = tags_sh[0];
        const int tl = tags_sh[LL - 1];
        float score = red[0]
                    + trans[t0 * TT + START_TAG]
                    + trans[STOP_TAG * TT + tl]
                    + in_b[(LL - 1) * TT + tl] * mf_sh[LL - 1];
        g_partials[b] = score - logden;
    }
}

// Deterministic fixed-order reduction of per-batch partials.
__global__ void __launch_bounds__(BB) crf_final_reduce_kernel(float* __restrict__ out)
{
    __shared__ float sh[BB];
    const int tid = threadIdx.x;
    sh[tid] = g_partials[tid];
    __syncthreads();
#pragma unroll
    for (int off = BB / 2; off > 0; off >>= 1) {
        if (tid < off) sh[tid] += sh[tid + off];
        __syncthreads();
    }
    if (tid == 0) out[0] = sh[0];
}

extern "C" void kernel_launch(void* const* d_in, const int* in_sizes, int n_in,
                              void* d_out, int out_size)
{
    const float* inputs = (const float*)d_in[0];
    const int*   tags   = (const int*)d_in[1];
    const int*   mask   = (const int*)d_in[2];
    const float* trans  = (const float*)d_in[3];

    crf_forward_kernel<<<BB, TT>>>(inputs, tags, mask, trans);
    crf_final_reduce_kernel<<<1, BB>>>((float*)d_out);
}

// round 2
// speedup vs baseline: 1.3973x; 1.3973x over previous
#include <cuda_runtime.h>
#include <cstddef>

#define TT 64
#define LL 512
#define BB 512
#define START_TAG 62
#define STOP_TAG  63

// Scratch (allocation-free requirement).
__device__ float g_partials[BB];
__device__ int   g_count;          // zero-initialized; reset by last block each launch

__device__ __forceinline__ void fma2(unsigned long long& acc,
                                     unsigned long long p,
                                     unsigned long long q) {
    asm("fma.rn.f32x2 %0, %1, %2, %0;" : "+l"(acc) : "l"(p), "l"(q));
}
__device__ __forceinline__ void add2(unsigned long long& a, unsigned long long b) {
    asm("add.rn.f32x2 %0, %0, %1;" : "+l"(a) : "l"(b));
}
__device__ __forceinline__ float2 unpack2(unsigned long long v) {
    float2 r;
    asm("mov.b64 {%0, %1}, %2;" : "=f"(r.x), "=f"(r.y) : "l"(v));
    return r;
}
__device__ __forceinline__ unsigned long long pack2(float lo, float hi) {
    unsigned long long v;
    asm("mov.b64 %0, {%1, %2};" : "=l"(v) : "f"(lo), "f"(hi));
    return v;
}

__global__ void __launch_bounds__(TT, 4) crf_fused_kernel(
    const float* __restrict__ inputs,   // (B, L, T)
    const int*   __restrict__ tags,     // (B, L)
    const int*   __restrict__ mask,     // (B, L)
    const float* __restrict__ trans,    // (T, T)
    float*       __restrict__ out)
{
    const int b   = blockIdx.x;
    const int tid = threadIdx.x;

    __shared__ __align__(16) float q_sh[2][TT];   // double-buffered q exchange
    __shared__ float dslot[2];                    // double-buffered lazy anchor
    __shared__ float mf_sh[LL];
    __shared__ int   tags_sh[LL];
    __shared__ float red[TT];
    __shared__ int   islast;

    // Packed exp(transition) row for destination tag = tid.
    unsigned long long P2[TT / 2];
#pragma unroll
    for (int j = 0; j < TT / 2; ++j) {
        float p0 = __expf(trans[tid * TT + 2 * j]);
        float p1 = __expf(trans[tid * TT + 2 * j + 1]);
        P2[j] = pack2(p0, p1);
    }

    // Stage mask / tags; detect all-ones mask.
    int m_and = 1;
    for (int t = tid; t < LL; t += TT) {
        int m = mask[b * LL + t];
        m_and &= (m != 0);
        mf_sh[t]   = (float)m;
        tags_sh[t] = tags[b * LL + t];
    }
    if (tid == 0) { dslot[0] = 0.0f; dslot[1] = 0.0f; }
    const int all_ones = __syncthreads_and(m_and);

    const float* emit_ptr = inputs + (size_t)b * LL * TT + tid;

    float a = (tid == START_TAG) ? 0.0f : -10000.0f;  // normalized log-alpha
    float C = 0.0f;                                   // accumulated offset

    if (all_ones) {
        // ---------- fast branchless path (mask == 1 everywhere) ----------
        float e0 = emit_ptr[0 * TT];
        float e1 = emit_ptr[1 * TT];
        float e2 = emit_ptr[2 * TT];
        float e3 = emit_ptr[3 * TT];

#pragma unroll 4
        for (int t = 0; t < LL; ++t) {
            float e_pf = (t + 4 < LL) ? emit_ptr[(t + 4) * TT] : 0.0f;

            const int buf = t & 1;
            q_sh[buf][tid] = __expf(a);
            __syncthreads();

            const float delta = dslot[(t + 1) & 1];   // d0 from step t-1 (0 at t=0)

            const ulonglong2* q4 = (const ulonglong2*)q_sh[buf];
            unsigned long long a0 = 0ull, a1 = 0ull, a2 = 0ull, a3 = 0ull;
#pragma unroll
            for (int k = 0; k < TT / 8; ++k) {        // 8 LDS.128, 16 FFMA2
                ulonglong2 v = q4[2 * k];
                ulonglong2 w = q4[2 * k + 1];
                fma2(a0, P2[4 * k + 0], v.x);
                fma2(a1, P2[4 * k + 1], v.y);
                fma2(a2, P2[4 * k + 2], w.x);
                fma2(a3, P2[4 * k + 3], w.y);
            }
            add2(a0, a1);
            add2(a2, a3);
            add2(a0, a2);
            float2 sp = unpack2(a0);
            const float s = sp.x + sp.y;

            float d = e0 + __logf(s);
            d = fmaxf(d, -1.0e30f);
            if (tid == 0) dslot[t & 1] = d;
            a = d - delta;
            C += delta;

            e0 = e1; e1 = e2; e2 = e3; e3 = e_pf;
        }
    } else {
        // ---------- general masked path (rare; round-1 proven logic) ----------
        float e_cur = emit_ptr[0];
        float e_nxt = emit_ptr[TT];
        for (int t = 0; t < LL; ++t) {
            float e_pf = (t + 2 < LL) ? emit_ptr[(t + 2) * TT] : 0.0f;

            q_sh[0][tid] = __expf(a);
            __syncthreads();

            const float mf = mf_sh[t];
            float s;
            if (mf != 0.0f) {
                const ulonglong2* q4 = (const ulonglong2*)q_sh[0];
                unsigned long long a0 = 0ull, a1 = 0ull, a2 = 0ull, a3 = 0ull;
#pragma unroll
                for (int k = 0; k < TT / 8; ++k) {
                    ulonglong2 v = q4[2 * k];
                    ulonglong2 w = q4[2 * k + 1];
                    fma2(a0, P2[4 * k + 0], v.x);
                    fma2(a1, P2[4 * k + 1], v.y);
                    fma2(a2, P2[4 * k + 2], w.x);
                    fma2(a3, P2[4 * k + 3], w.y);
                }
                add2(a0, a1);
                add2(a2, a3);
                add2(a0, a2);
                float2 sp = unpack2(a0);
                s = sp.x + sp.y;
            } else {
                float acc = 0.f;
#pragma unroll
                for (int j = 0; j < TT; ++j) acc += q_sh[0][j];
                s = acc;
            }

            float d = fmaf(mf, e_cur, __logf(s));
            d = fmaxf(d, -1.0e30f);
            if (tid == 0) dslot[0] = d;
            __syncthreads();
            const float d0 = dslot[0];
            a = d - d0;
            C += d0;

            e_cur = e_nxt;
            e_nxt = e_pf;
        }
    }

    // ---- log denominator: C + logsumexp(a + trans[STOP, :]) ----
    const float term = a + trans[STOP_TAG * TT + tid];
    red[tid] = term;
    __syncthreads();
#pragma unroll
    for (int off = TT / 2; off > 0; off >>= 1) {
        if (tid < off) red[tid] = fmaxf(red[tid], red[tid + off]);
        __syncthreads();
    }
    const float mx = red[0];
    __syncthreads();
    red[tid] = __expf(term - mx);
    __syncthreads();
#pragma unroll
    for (int off = TT / 2; off > 0; off >>= 1) {
        if (tid < off) red[tid] += red[tid + off];
        __syncthreads();
    }
    const float logden = C + mx + __logf(red[0]);
    __syncthreads();

    // ---- numerator path score (gold tags) ----
    float sc = 0.f;
    const float* in_b = inputs + (size_t)b * LL * TT;
    for (int t = tid; t < LL - 1; t += TT) {
        const int pt = tags_sh[t];
        const int nt = tags_sh[t + 1];
        sc += trans[nt * TT + pt] * mf_sh[t + 1] + in_b[t * TT + pt] * mf_sh[t];
    }
    red[tid] = sc;
    __syncthreads();
#pragma unroll
    for (int off = TT / 2; off > 0; off >>= 1) {
        if (tid < off) red[tid] += red[tid + off];
        __syncthreads();
    }
    if (tid == 0) {
        const int t0 = tags_sh[0];
        const int tl = tags_sh[LL - 1];
        float score = red[0]
                    + trans[t0 * TT + START_TAG]
                    + trans[STOP_TAG * TT + tl]
                    + in_b[(LL - 1) * TT + tl] * mf_sh[LL - 1];
        g_partials[b] = score - logden;
    }

    // ---- deterministic fixed-order final reduction in the last block ----
    if (tid == 0) {
        __threadfence();
        int old = atomicAdd(&g_count, 1);
        islast = (old == (int)gridDim.x - 1);
    }
    __syncthreads();
    if (islast) {
        __threadfence();
        float s = 0.f;
#pragma unroll
        for (int k = 0; k < BB / TT; ++k)        // fixed order: 8 sequential adds
            s += g_partials[tid * (BB / TT) + k];
        red[tid] = s;
        __syncthreads();
#pragma unroll
        for (int off = TT / 2; off > 0; off >>= 1) {
            if (tid < off) red[tid] += red[tid + off];
            __syncthreads();
        }
        if (tid == 0) {
            out[0] = red[0];
            g_count = 0;                         // reset for next graph replay
        }
    }
}

extern "C" void kernel_launch(void* const* d_in, const int* in_sizes, int n_in,
                              void* d_out, int out_size)
{
    const float* inputs = (const float*)d_in[0];
    const int*   tags   = (const int*)d_in[1];
    const int*   mask   = (const int*)d_in[2];
    const float* trans  = (const float*)d_in[3];

    crf_fused_kernel<<<BB, TT>>>(inputs, tags, mask, trans, (float*)d_out);
}